// round 10
// baseline (speedup 1.0000x reference)
#include <cuda_runtime.h>

#define N0   8192
#define NK1  4096
#define NK2  2048
#define FD   32
#define FIN  16
#define ELLW 512
#define EPSV 1e-10f

// ---------------- device scratch (static; no allocation) ----------------
__device__ unsigned short g_ell [(size_t)N0  * ELLW]; // 8 MB
__device__ unsigned short g_ell1[(size_t)NK1 * ELLW]; // 4 MB
__device__ int   g_cnt  [N0];
__device__ int   g_cnt1 [NK1];
__device__ float g_dinv [N0];
__device__ float g_dinv1[NK1];
__device__ float g_Yx[N0 * FIN];  // d ∘ x  (16-wide gather payload, layer 1)
__device__ float g_Y [NK1 * FD];  // d1 ∘ (X1[idx1] @ W2) (layer-2 payload)
__device__ float g_X1[N0 * FD];
__device__ float g_X2[NK1 * FD];
__device__ float g_X3[NK1 * FD];
__device__ float g_md[NK1];       // mask * d1 (for fused spmm3)
__device__ float g_sc[N0];
__device__ float g_Y2[N0 * 2];
__device__ int g_idx1[NK1];
__device__ int g_pos1[N0];
__device__ int g_idx2[NK2];
__device__ int g_pos2[NK1];

// ------- 1) ELL build + degrees + Yx = d∘x (one 256MB streaming read) ---
__global__ void __launch_bounds__(256) k_build_ell(const float* __restrict__ a,
                                                   const float* __restrict__ x) {
    int row  = blockIdx.x * 8 + (threadIdx.x >> 5);
    int lane = threadIdx.x & 31;
    const float4* arow = reinterpret_cast<const float4*>(a + (size_t)row * N0);
    unsigned short* out = g_ell + (size_t)row * ELLW;
    int cnt = 0;
#pragma unroll
    for (int it = 0; it < 8; it++) {
        float4 v[8];
#pragma unroll
        for (int j = 0; j < 8; j++) v[j] = __ldcs(&arow[it * 256 + j * 32 + lane]);
        unsigned msk = 0u;
#pragma unroll
        for (int j = 0; j < 8; j++) {
            float vs[4] = { v[j].x, v[j].y, v[j].z, v[j].w };
#pragma unroll
            for (int s = 0; s < 4; s++)
                msk |= (vs[s] != 0.0f ? 1u : 0u) << (j * 4 + s);
        }
        int nl = __popc(msk);
        int inc = nl;
#pragma unroll
        for (int off = 1; off < 32; off <<= 1) {
            int t = __shfl_up_sync(0xffffffffu, inc, off);
            if (lane >= off) inc += t;
        }
        int base = cnt + (inc - nl);
        int tot  = __shfl_sync(0xffffffffu, inc, 31);
        int cbase = it * 1024 + lane * 4;
        while (msk) {
            int b = __ffs(msk) - 1;
            msk &= msk - 1;
            int col = cbase + (b >> 2) * 128 + (b & 3);
            if (base < ELLW) out[base] = (unsigned short)col;
            base++;
        }
        cnt += tot;
    }
    float dinv = rsqrtf((float)cnt + 1.0f + EPSV);
    if (lane == 0) {
        g_cnt[row]  = cnt < ELLW ? cnt : ELLW;
        g_dinv[row] = dinv;
    }
    if (lane < FIN) g_Yx[row * FIN + lane] = dinv * x[row * FIN + lane];
}

// ------- spmm1: X1 = relu( (d∘(A+I)(d∘x)) @ W1 ), fused scores1 ---------
// 2 warps per row; each warp's lane halves split neighbors 4 ways total.
__global__ void k_spmm1(const float* __restrict__ W1,
                        const float* __restrict__ s1) {
    __shared__ float sW[FIN * FD];
    __shared__ float ssv[FD];
    __shared__ float sP[8][FIN];
    for (int i = threadIdx.x; i < FIN * FD; i += blockDim.x) sW[i] = W1[i];
    if (threadIdx.x < FD) ssv[threadIdx.x] = s1[threadIdx.x];
    __syncthreads();
    int w    = threadIdx.x >> 5;
    int row  = blockIdx.x * 4 + (w >> 1);
    int half2 = w & 1;                 // which warp of the pair
    int lane = threadIdx.x & 31;
    int h    = lane & 15;              // feature
    int qh   = lane >> 4;              // neighbor sub-half within warp
    const unsigned short* cols = g_ell + (size_t)row * ELLW;
    const uint4* cp = reinterpret_cast<const uint4*>(cols);
    int c = g_cnt[row];
    float acc = (half2 == 0 && qh == 0) ? g_Yx[row * FIN + h] : 0.f; // self
    int nv = c >> 3;
    for (int i = half2; i < nv; i += 2) {
        uint4 q = cp[i];
        int c0, c1, c2, c3;
        if (qh == 0) { c0 = q.x & 0xffff; c1 = q.x >> 16; c2 = q.y & 0xffff; c3 = q.y >> 16; }
        else         { c0 = q.z & 0xffff; c1 = q.z >> 16; c2 = q.w & 0xffff; c3 = q.w >> 16; }
        float v0 = __ldg(&g_Yx[c0 * FIN + h]);
        float v1 = __ldg(&g_Yx[c1 * FIN + h]);
        float v2 = __ldg(&g_Yx[c2 * FIN + h]);
        float v3 = __ldg(&g_Yx[c3 * FIN + h]);
        acc += (v0 + v1) + (v2 + v3);
    }
    for (int t = nv * 8 + half2 * 2 + qh; t < c; t += 4)
        acc += __ldg(&g_Yx[cols[t] * FIN + h]);
    acc += __shfl_down_sync(0xffffffffu, acc, 16);
    if (qh == 0) sP[w][h] = acc;
    __syncthreads();
    if (half2 == 0) {
        float d = g_dinv[row];
        float o = 0.f;
#pragma unroll
        for (int kk = 0; kk < FIN; kk++)
            o += (sP[w][kk] + sP[w + 1][kk]) * sW[kk * FD + lane];
        o = fmaxf(d * o, 0.f);
        g_X1[row * FD + lane] = o;
        float p = o * ssv[lane];
#pragma unroll
        for (int off = 16; off > 0; off >>= 1)
            p += __shfl_down_sync(0xffffffffu, p, off);
        if (lane == 0) g_sc[row] = p;
    }
}

// ------- top-k: radix-select threshold + stable lowest-index ties -------
template <int SIZE, int CH>
__global__ void k_topk(int k, int osel) {
    __shared__ unsigned hist[256];
    __shared__ unsigned warpsum[32];
    __shared__ unsigned s_byte;
    __shared__ int s_kr;
    int tid  = threadIdx.x;
    int lane = tid & 31;
    int wid  = tid >> 5;
    unsigned keys[CH];
#pragma unroll
    for (int c = 0; c < CH; c++) {
        unsigned u = __float_as_uint(g_sc[tid * CH + c]);
        keys[c] = (u & 0x80000000u) ? ~u : (u | 0x80000000u); // order-preserving
    }
    unsigned prefix = 0;
    int kr = k;
    for (int round = 0; round < 4; round++) {
        int sh = 24 - round * 8;
        if (tid < 256) hist[tid] = 0u;
        __syncthreads();
        unsigned pmask = (round == 0) ? 0u : (0xffffffffu << (sh + 8));
#pragma unroll
        for (int c = 0; c < CH; c++) {
            if ((keys[c] & pmask) == prefix)
                atomicAdd(&hist[(keys[c] >> sh) & 0xffu], 1u);
        }
        __syncthreads();
        if (wid == 0) {
            unsigned h[8];
#pragma unroll
            for (int i = 0; i < 8; i++) h[i] = hist[lane * 8 + i];
            unsigned loc[8];
            unsigned run = 0;
#pragma unroll
            for (int i = 7; i >= 0; i--) { run += h[i]; loc[i] = run; }
            unsigned s = run;
#pragma unroll
            for (int off = 1; off < 32; off <<= 1) {
                unsigned t = __shfl_down_sync(0xffffffffu, s, off);
                if (lane + off < 32) s += t;
            }
            unsigned higher = s - run;
#pragma unroll
            for (int i = 0; i < 8; i++) {
                unsigned S = loc[i] + higher;
                if (S >= (unsigned)kr && (S - h[i]) < (unsigned)kr) {
                    s_byte = (unsigned)(lane * 8 + i);
                    s_kr   = kr - (int)(S - h[i]);
                }
            }
        }
        __syncthreads();
        prefix |= (s_byte << sh);
        kr = s_kr;
        __syncthreads();
    }
    unsigned thr = prefix; // exact k-th largest key

    int nstrict = 0, neq = 0;
#pragma unroll
    for (int c = 0; c < CH; c++) {
        nstrict += (keys[c] > thr);
        neq     += (keys[c] == thr);
    }
    unsigned v = ((unsigned)nstrict << 16) | (unsigned)neq;
    unsigned sc = v;
#pragma unroll
    for (int off = 1; off < 32; off <<= 1) {
        unsigned t = __shfl_up_sync(0xffffffffu, sc, off);
        if (lane >= off) sc += t;
    }
    if (lane == 31) warpsum[wid] = sc;
    __syncthreads();
    if (wid == 0) {
        unsigned w = warpsum[lane];
        unsigned ws = w;
#pragma unroll
        for (int off = 1; off < 32; off <<= 1) {
            unsigned t = __shfl_up_sync(0xffffffffu, ws, off);
            if (lane >= off) ws += t;
        }
        warpsum[lane] = ws;
    }
    __syncthreads();
    unsigned incl  = sc + (wid > 0 ? warpsum[wid - 1] : 0u);
    unsigned total = warpsum[31];
    unsigned excl  = incl - v;
    int st = (int)(excl >> 16);
    int eq = (int)(excl & 0xffffu);
    int budget = k - (int)(total >> 16); // ties filled by lowest index
    int* idx = (osel == 0) ? g_idx1 : g_idx2;
    int* pos = (osel == 0) ? g_pos1 : g_pos2;
#pragma unroll
    for (int c = 0; c < CH; c++) {
        unsigned key = keys[c];
        int i = tid * CH + c;
        bool isS = (key > thr);
        bool isE = (key == thr);
        bool sel = isS || (isE && eq < budget);
        int p = -1;
        if (sel) {
            int rank = st + (eq < budget ? eq : budget);
            idx[rank] = i;
            p = rank;
        }
        pos[i] = p;
        st += isS;
        eq += isE;
        if (osel == 1) g_md[i] = (p >= 0) ? g_dinv1[i] : 0.f; // mask*d1 for spmm3
    }
}

// ------- sub-graph ELL: A1p = a[idx1][:,idx1]; fused mm2 ----------------
// Lane owns 8 contiguous entries; segment 2 only touched when c > 256
// (degrees are ~163±13, so essentially never). Output order scrambled
// (allowed: ELL1 consumers are order-invariant).
__global__ void k_sub_ell(const float* __restrict__ W2) {
    __shared__ float sW[FD * FD];
    for (int i = threadIdx.x; i < FD * FD; i += blockDim.x) sW[i] = W2[i];
    __syncthreads();
    int r    = blockIdx.x * 8 + (threadIdx.x >> 5);
    int lane = threadIdx.x & 31;
    int src  = g_idx1[r];
    int c    = g_cnt[src];
    const uint4* inv4 = reinterpret_cast<const uint4*>(g_ell + (size_t)src * ELLW);
    unsigned short* out = g_ell1 + (size_t)r * ELLW;
    int oc = 0;
    for (int seg = 0; seg == 0 || seg * 256 < c; seg++) {
        int base = seg * 256 + lane * 8;
        int pc[8];
        if (base < c) {
            uint4 q = inv4[seg * 32 + lane];
            unsigned short e[8] = {
                (unsigned short)(q.x & 0xffff), (unsigned short)(q.x >> 16),
                (unsigned short)(q.y & 0xffff), (unsigned short)(q.y >> 16),
                (unsigned short)(q.z & 0xffff), (unsigned short)(q.z >> 16),
                (unsigned short)(q.w & 0xffff), (unsigned short)(q.w >> 16) };
#pragma unroll
            for (int u = 0; u < 8; u++)
                pc[u] = (base + u < c) ? g_pos1[e[u]] : -1;
        } else {
#pragma unroll
            for (int u = 0; u < 8; u++) pc[u] = -1;
        }
        int myn = 0;
#pragma unroll
        for (int u = 0; u < 8; u++) myn += (pc[u] >= 0);
        int inc = myn;
#pragma unroll
        for (int off = 1; off < 32; off <<= 1) {
            int t = __shfl_up_sync(0xffffffffu, inc, off);
            if (lane >= off) inc += t;
        }
        int wbase = oc + (inc - myn);
        int tot   = __shfl_sync(0xffffffffu, inc, 31);
#pragma unroll
        for (int u = 0; u < 8; u++) {
            if (pc[u] >= 0) { out[wbase] = (unsigned short)pc[u]; wbase++; }
        }
        oc += tot;
        if (seg == 1) break;
    }
    float dinv1 = rsqrtf((float)oc + 1.0f + EPSV);
    if (lane == 0) {
        g_cnt1[r]  = oc;
        g_dinv1[r] = dinv1;
    }
    // fused mm2: Y = d1 .* (X1[idx1] @ W2)
    float x1v = g_X1[src * FD + lane];
    float acc = 0.f;
#pragma unroll
    for (int kk = 0; kk < FD; kk++)
        acc += __shfl_sync(0xffffffffu, x1v, kk) * sW[kk * FD + lane];
    g_Y[r * FD + lane] = dinv1 * acc;
}

// ------- spmm2: X2 = relu(d1∘((A1+I) Y)), fused scores2 (2 warps/row) ---
__global__ void k_spmm2(const float* __restrict__ s2) {
    __shared__ float ssv[FD];
    __shared__ float sP[8][FD];
    if (threadIdx.x < FD) ssv[threadIdx.x] = s2[threadIdx.x];
    __syncthreads();
    int w    = threadIdx.x >> 5;
    int row  = blockIdx.x * 4 + (w >> 1);
    int half = w & 1;
    int lane = threadIdx.x & 31;
    const unsigned short* cols = g_ell1 + (size_t)row * ELLW;
    const uint4* cp = reinterpret_cast<const uint4*>(cols);
    int c = g_cnt1[row];
    float acc = (half == 0) ? g_Y[row * FD + lane] : 0.f;  // self
    int nv = c >> 3;
    for (int i = half; i < nv; i += 2) {
        uint4 q = cp[i];
        int c0 = q.x & 0xffff, c1 = q.x >> 16;
        int c2 = q.y & 0xffff, c3 = q.y >> 16;
        int c4 = q.z & 0xffff, c5 = q.z >> 16;
        int c6 = q.w & 0xffff, c7 = q.w >> 16;
        float v0 = __ldg(&g_Y[c0 * FD + lane]);
        float v1 = __ldg(&g_Y[c1 * FD + lane]);
        float v2 = __ldg(&g_Y[c2 * FD + lane]);
        float v3 = __ldg(&g_Y[c3 * FD + lane]);
        float v4 = __ldg(&g_Y[c4 * FD + lane]);
        float v5 = __ldg(&g_Y[c5 * FD + lane]);
        float v6 = __ldg(&g_Y[c6 * FD + lane]);
        float v7 = __ldg(&g_Y[c7 * FD + lane]);
        acc += ((v0 + v1) + (v2 + v3)) + ((v4 + v5) + (v6 + v7));
    }
    for (int t = nv * 8 + half; t < c; t += 2)
        acc += __ldg(&g_Y[cols[t] * FD + lane]);
    sP[w][lane] = acc;
    __syncthreads();
    if (half == 0) {
        float ov = fmaxf(g_dinv1[row] * (sP[w][lane] + sP[w + 1][lane]), 0.f);
        g_X2[row * FD + lane] = ov;
        float p = ov * ssv[lane];
#pragma unroll
        for (int o = 16; o > 0; o >>= 1) p += __shfl_down_sync(0xffffffffu, p, o);
        if (lane == 0) g_sc[row] = p;
    }
}

// ------- spmm3: X3 = relu(d1 .* ( ((A1+I)(md∘X2)) @ W3 )) (2 warps/row) -
__global__ void k_spmm3(const float* __restrict__ W3) {
    __shared__ float sW[FD * FD];
    __shared__ float sP[8][FD];
    for (int i = threadIdx.x; i < FD * FD; i += blockDim.x) sW[i] = W3[i];
    __syncthreads();
    int w    = threadIdx.x >> 5;
    int row  = blockIdx.x * 4 + (w >> 1);
    int half = w & 1;
    int lane = threadIdx.x & 31;
    const unsigned short* cols = g_ell1 + (size_t)row * ELLW;
    const uint4* cp = reinterpret_cast<const uint4*>(cols);
    int c = g_cnt1[row];
    float acc = (half == 0) ? g_md[row] * g_X2[row * FD + lane] : 0.f;  // self
    int nv = c >> 3;
    for (int i = half; i < nv; i += 2) {
        uint4 q = cp[i];
        int c0 = q.x & 0xffff, c1 = q.x >> 16;
        int c2 = q.y & 0xffff, c3 = q.y >> 16;
        int c4 = q.z & 0xffff, c5 = q.z >> 16;
        int c6 = q.w & 0xffff, c7 = q.w >> 16;
        acc += __ldg(&g_md[c0]) * __ldg(&g_X2[c0 * FD + lane]);
        acc += __ldg(&g_md[c1]) * __ldg(&g_X2[c1 * FD + lane]);
        acc += __ldg(&g_md[c2]) * __ldg(&g_X2[c2 * FD + lane]);
        acc += __ldg(&g_md[c3]) * __ldg(&g_X2[c3 * FD + lane]);
        acc += __ldg(&g_md[c4]) * __ldg(&g_X2[c4 * FD + lane]);
        acc += __ldg(&g_md[c5]) * __ldg(&g_X2[c5 * FD + lane]);
        acc += __ldg(&g_md[c6]) * __ldg(&g_X2[c6 * FD + lane]);
        acc += __ldg(&g_md[c7]) * __ldg(&g_X2[c7 * FD + lane]);
    }
    for (int t = nv * 8 + half; t < c; t += 2) {
        int cc = cols[t];
        acc += __ldg(&g_md[cc]) * __ldg(&g_X2[cc * FD + lane]);
    }
    sP[w][lane] = acc;
    __syncthreads();
    if (half == 0) {
        float o = 0.f;
#pragma unroll
        for (int kk = 0; kk < FD; kk++)
            o += (sP[w][kk] + sP[w + 1][kk]) * sW[kk * FD + lane];
        g_X3[row * FD + lane] = fmaxf(g_dinv1[row] * o, 0.f);
    }
}

// ---------------- mm4: unpool to N0 + scale (warp/row, coalesced) -------
__global__ void k_mm4(const float* __restrict__ W4) {
    __shared__ float sw0[FD], sw1[FD];
    if (threadIdx.x < FD) {
        sw0[threadIdx.x] = W4[threadIdx.x * 2];
        sw1[threadIdx.x] = W4[threadIdx.x * 2 + 1];
    }
    __syncthreads();
    int i    = blockIdx.x * 8 + (threadIdx.x >> 5);
    int lane = threadIdx.x & 31;
    int p = g_pos1[i];
    float a0 = 0.f, a1 = 0.f;
    if (p >= 0) {
        float v = g_X3[p * FD + lane] * g_dinv[i];
        a0 = v * sw0[lane];
        a1 = v * sw1[lane];
    }
#pragma unroll
    for (int o = 16; o > 0; o >>= 1) {
        a0 += __shfl_down_sync(0xffffffffu, a0, o);
        a1 += __shfl_down_sync(0xffffffffu, a1, o);
    }
    if (lane == 0) {
        float2* y2 = reinterpret_cast<float2*>(g_Y2);
        y2[i] = make_float2(a0, a1);
    }
}

// ---------------- final 2-wide SpMM + softmax (16 lanes/row) ------------
__global__ void k_out(float* __restrict__ out) {
    int row = blockIdx.x * 16 + (threadIdx.x >> 4);
    int l   = threadIdx.x & 15;
    const unsigned short* cols = g_ell + (size_t)row * ELLW;
    int c = g_cnt[row];
    const float2* y2 = reinterpret_cast<const float2*>(g_Y2);
    float s0 = 0.f, s1 = 0.f;
    for (int t = l; t < c; t += 16) {
        float2 v = __ldg(&y2[cols[t]]);
        s0 += v.x; s1 += v.y;
    }
#pragma unroll
    for (int o = 8; o > 0; o >>= 1) {
        s0 += __shfl_down_sync(0xffffffffu, s0, o, 16);
        s1 += __shfl_down_sync(0xffffffffu, s1, o, 16);
    }
    if (l == 0) {
        float d  = g_dinv[row];
        float2 self = y2[row];
        float z0 = d * (s0 + self.x);
        float z1 = d * (s1 + self.y);
        float m  = fmaxf(z0, z1);
        float e0 = expf(z0 - m), e1 = expf(z1 - m);
        float inv = 1.f / (e0 + e1);
        out[row * 2]     = e0 * inv;
        out[row * 2 + 1] = e1 * inv;
    }
}

// ---------------- launch ------------------------------------------------
extern "C" void kernel_launch(void* const* d_in, const int* in_sizes, int n_in,
                              void* d_out, int out_size) {
    const float* x  = (const float*)d_in[0];
    const float* a  = (const float*)d_in[1];
    const float* W1 = (const float*)d_in[2];
    const float* W2 = (const float*)d_in[3];
    const float* W3 = (const float*)d_in[4];
    const float* W4 = (const float*)d_in[5];
    const float* s1 = (const float*)d_in[6];
    const float* s2 = (const float*)d_in[7];
    float* out = (float*)d_out;

    k_build_ell<<<N0 / 8, 256>>>(a, x);              // ELL + deg + Yx=d∘x
    k_spmm1<<<N0 / 4, 256>>>(W1, s1);                // X1 (2 warps/row) + scores1
    k_topk<8192, 8><<<1, 1024>>>(NK1, 0);            // idx1/pos1
    k_sub_ell<<<NK1 / 8, 256>>>(W2);                 // ELL1 + d1 + Y=d1∘(X1[idx1]@W2)
    k_spmm2<<<NK1 / 4, 256>>>(s2);                   // X2 (2 warps/row) + scores2
    k_topk<4096, 4><<<1, 1024>>>(NK2, 1);            // pos2 + md
    k_spmm3<<<NK1 / 4, 256>>>(W3);                   // X3 (2 warps/row)
    k_mm4<<<N0 / 8, 256>>>(W4);                      // Y2 (8192x2)
    k_out<<<N0 / 16, 256>>>(out);                    // softmax(A_norm @ Y2)
}

// round 12
// speedup vs baseline: 1.0754x; 1.0754x over previous
#include <cuda_runtime.h>

#define N0   8192
#define NK1  4096
#define NK2  2048
#define FD   32
#define FIN  16
#define ELLW 512
#define EPSV 1e-10f

// ---------------- device scratch (static; no allocation) ----------------
__device__ unsigned short g_ell [(size_t)N0  * ELLW]; // 8 MB
__device__ unsigned short g_ell1[(size_t)NK1 * ELLW]; // 4 MB
__device__ int   g_cnt  [N0];
__device__ int   g_cnt1 [NK1];
__device__ float g_dinv [N0];
__device__ float g_dinv1[NK1];
__device__ float g_Yx[N0 * FIN];  // d ∘ x  (16-wide gather payload, layer 1)
__device__ float g_Y [NK1 * FD];  // d1 ∘ (X1[idx1] @ W2) (layer-2 payload)
__device__ float g_X1[N0 * FD];
__device__ float g_X2[NK1 * FD];
__device__ float g_md[NK1];       // mask * d1 (for fused spmm3)
__device__ float g_sc[N0];
__device__ float g_Y2[N0 * 2];
__device__ int g_idx1[NK1];
__device__ int g_pos1[N0];
__device__ int g_idx2[NK2];
__device__ int g_pos2[NK1];

// ------- 1) ELL build + degrees + Yx = d∘x (one 256MB streaming read) ---
__global__ void k_build_ell(const float* __restrict__ a,
                            const float* __restrict__ x) {
    int row  = blockIdx.x * 8 + (threadIdx.x >> 5);
    int lane = threadIdx.x & 31;
    const float4* arow = reinterpret_cast<const float4*>(a + (size_t)row * N0);
    unsigned short* out = g_ell + (size_t)row * ELLW;
    float4 bufA[8], bufB[8];
#pragma unroll
    for (int j = 0; j < 8; j++) bufA[j] = __ldcs(&arow[j * 32 + lane]);
    int cnt = 0;
#pragma unroll
    for (int it = 0; it < 8; it++) {
        float4* cur = (it & 1) ? bufB : bufA;
        float4* nxt = (it & 1) ? bufA : bufB;
        if (it < 7) {
#pragma unroll
            for (int j = 0; j < 8; j++)
                nxt[j] = __ldcs(&arow[(it + 1) * 256 + j * 32 + lane]);
        }
        unsigned msk = 0u;
#pragma unroll
        for (int j = 0; j < 8; j++) {
            float vs[4] = { cur[j].x, cur[j].y, cur[j].z, cur[j].w };
#pragma unroll
            for (int s = 0; s < 4; s++)
                msk |= (vs[s] != 0.0f ? 1u : 0u) << (j * 4 + s);
        }
        int nl = __popc(msk);
        int inc = nl;
#pragma unroll
        for (int off = 1; off < 32; off <<= 1) {
            int t = __shfl_up_sync(0xffffffffu, inc, off);
            if (lane >= off) inc += t;
        }
        int base = cnt + (inc - nl);
        int tot  = __shfl_sync(0xffffffffu, inc, 31);
        int cbase = it * 1024 + lane * 4;
        while (msk) {
            int b = __ffs(msk) - 1;
            msk &= msk - 1;
            int col = cbase + (b >> 2) * 128 + (b & 3);
            if (base < ELLW) out[base] = (unsigned short)col;
            base++;
        }
        cnt += tot;
    }
    float dinv = rsqrtf((float)cnt + 1.0f + EPSV);
    if (lane == 0) {
        g_cnt[row]  = cnt < ELLW ? cnt : ELLW;
        g_dinv[row] = dinv;
    }
    if (lane < FIN) g_Yx[row * FIN + lane] = dinv * x[row * FIN + lane];
}

// ------- spmm1: X1 = relu( (d∘(A+I)(d∘x)) @ W1 ), fused scores1 ---------
// Gather is 16-wide (64B/row) — W1 applied once per row afterwards.
// Lane split: half 0 (lanes 0-15) handles even neighbors, half 1 odd.
__global__ void k_spmm1(const float* __restrict__ W1,
                        const float* __restrict__ s1) {
    __shared__ float sW[FIN * FD];
    __shared__ float ssv[FD];
    __shared__ float sS[8][FIN];
    for (int i = threadIdx.x; i < FIN * FD; i += blockDim.x) sW[i] = W1[i];
    if (threadIdx.x < FD) ssv[threadIdx.x] = s1[threadIdx.x];
    __syncthreads();
    int w    = threadIdx.x >> 5;
    int row  = blockIdx.x * 8 + w;
    int lane = threadIdx.x & 31;
    int h    = lane & 15;
    int half = lane >> 4;
    const unsigned short* cols = g_ell + (size_t)row * ELLW;
    const uint4* cp = reinterpret_cast<const uint4*>(cols);
    int c = g_cnt[row];
    float acc = (half == 0) ? g_Yx[row * FIN + h] : 0.f;  // self term
    int nv = c >> 3;
    for (int i = 0; i < nv; i++) {
        uint4 q = cp[i];
        int c0, c1, c2, c3;
        if (half == 0) { c0 = q.x & 0xffff; c1 = q.x >> 16; c2 = q.y & 0xffff; c3 = q.y >> 16; }
        else           { c0 = q.z & 0xffff; c1 = q.z >> 16; c2 = q.w & 0xffff; c3 = q.w >> 16; }
        float v0 = __ldg(&g_Yx[c0 * FIN + h]);
        float v1 = __ldg(&g_Yx[c1 * FIN + h]);
        float v2 = __ldg(&g_Yx[c2 * FIN + h]);
        float v3 = __ldg(&g_Yx[c3 * FIN + h]);
        acc += (v0 + v1) + (v2 + v3);
    }
    for (int t = nv * 8 + half; t < c; t += 2)
        acc += __ldg(&g_Yx[cols[t] * FIN + h]);
    acc += __shfl_down_sync(0xffffffffu, acc, 16);
    if (half == 0) sS[w][h] = g_dinv[row] * acc;
    __syncwarp();
    float o = 0.f;
#pragma unroll
    for (int kk = 0; kk < FIN; kk++) o += sS[w][kk] * sW[kk * FD + lane];
    o = fmaxf(o, 0.f);
    g_X1[row * FD + lane] = o;
    float p = o * ssv[lane];
#pragma unroll
    for (int off = 16; off > 0; off >>= 1) p += __shfl_down_sync(0xffffffffu, p, off);
    if (lane == 0) g_sc[row] = p;
}

// ------- top-k: radix-select threshold + stable lowest-index ties -------
template <int SIZE, int CH>
__global__ void k_topk(int k, int osel) {
    __shared__ unsigned hist[256];
    __shared__ unsigned warpsum[32];
    __shared__ unsigned s_byte;
    __shared__ int s_kr;
    int tid  = threadIdx.x;
    int lane = tid & 31;
    int wid  = tid >> 5;
    unsigned keys[CH];
#pragma unroll
    for (int c = 0; c < CH; c++) {
        unsigned u = __float_as_uint(g_sc[tid * CH + c]);
        keys[c] = (u & 0x80000000u) ? ~u : (u | 0x80000000u); // order-preserving
    }
    unsigned prefix = 0;
    int kr = k;
    for (int round = 0; round < 4; round++) {
        int sh = 24 - round * 8;
        if (tid < 256) hist[tid] = 0u;
        __syncthreads();
        unsigned pmask = (round == 0) ? 0u : (0xffffffffu << (sh + 8));
#pragma unroll
        for (int c = 0; c < CH; c++) {
            if ((keys[c] & pmask) == prefix)
                atomicAdd(&hist[(keys[c] >> sh) & 0xffu], 1u);
        }
        __syncthreads();
        if (wid == 0) {
            unsigned h[8];
#pragma unroll
            for (int i = 0; i < 8; i++) h[i] = hist[lane * 8 + i];
            unsigned loc[8];
            unsigned run = 0;
#pragma unroll
            for (int i = 7; i >= 0; i--) { run += h[i]; loc[i] = run; }
            unsigned s = run;
#pragma unroll
            for (int off = 1; off < 32; off <<= 1) {
                unsigned t = __shfl_down_sync(0xffffffffu, s, off);
                if (lane + off < 32) s += t;
            }
            unsigned higher = s - run;
#pragma unroll
            for (int i = 0; i < 8; i++) {
                unsigned S = loc[i] + higher;
                if (S >= (unsigned)kr && (S - h[i]) < (unsigned)kr) {
                    s_byte = (unsigned)(lane * 8 + i);
                    s_kr   = kr - (int)(S - h[i]);
                }
            }
        }
        __syncthreads();
        prefix |= (s_byte << sh);
        kr = s_kr;
        __syncthreads();
    }
    unsigned thr = prefix; // exact k-th largest key

    int nstrict = 0, neq = 0;
#pragma unroll
    for (int c = 0; c < CH; c++) {
        nstrict += (keys[c] > thr);
        neq     += (keys[c] == thr);
    }
    unsigned v = ((unsigned)nstrict << 16) | (unsigned)neq;
    unsigned sc = v;
#pragma unroll
    for (int off = 1; off < 32; off <<= 1) {
        unsigned t = __shfl_up_sync(0xffffffffu, sc, off);
        if (lane >= off) sc += t;
    }
    if (lane == 31) warpsum[wid] = sc;
    __syncthreads();
    if (wid == 0) {
        unsigned w = warpsum[lane];
        unsigned ws = w;
#pragma unroll
        for (int off = 1; off < 32; off <<= 1) {
            unsigned t = __shfl_up_sync(0xffffffffu, ws, off);
            if (lane >= off) ws += t;
        }
        warpsum[lane] = ws;
    }
    __syncthreads();
    unsigned incl  = sc + (wid > 0 ? warpsum[wid - 1] : 0u);
    unsigned total = warpsum[31];
    unsigned excl  = incl - v;
    int st = (int)(excl >> 16);
    int eq = (int)(excl & 0xffffu);
    int budget = k - (int)(total >> 16); // ties filled by lowest index
    int* idx = (osel == 0) ? g_idx1 : g_idx2;
    int* pos = (osel == 0) ? g_pos1 : g_pos2;
#pragma unroll
    for (int c = 0; c < CH; c++) {
        unsigned key = keys[c];
        int i = tid * CH + c;
        bool isS = (key > thr);
        bool isE = (key == thr);
        bool sel = isS || (isE && eq < budget);
        int p = -1;
        if (sel) {
            int rank = st + (eq < budget ? eq : budget);
            idx[rank] = i;
            p = rank;
        }
        pos[i] = p;
        st += isS;
        eq += isE;
        if (osel == 1) g_md[i] = (p >= 0) ? g_dinv1[i] : 0.f; // mask*d1 for spmm3
    }
    // pre-zero Y2 (runs before spmm3; selected entries overwritten there)
    if (osel == 0) {
        float2* y2 = reinterpret_cast<float2*>(g_Y2);
        for (int i = tid; i < N0; i += 1024) y2[i] = make_float2(0.f, 0.f);
    }
}

// ------- sub-graph ELL: A1p = a[idx1][:,idx1]; fused mm2 ----------------
// Lane owns 8 contiguous entries (one uint4 load, 8 independent pos1
// gathers). Compaction = 2 warp scans; output order scrambled (allowed:
// all ELL1 consumers are order-invariant).
__global__ void k_sub_ell(const float* __restrict__ W2) {
    __shared__ float sW[FD * FD];
    for (int i = threadIdx.x; i < FD * FD; i += blockDim.x) sW[i] = W2[i];
    __syncthreads();
    int r    = blockIdx.x * 8 + (threadIdx.x >> 5);
    int lane = threadIdx.x & 31;
    int src  = g_idx1[r];
    int c    = g_cnt[src];
    const uint4* inv4 = reinterpret_cast<const uint4*>(g_ell + (size_t)src * ELLW);
    unsigned short* out = g_ell1 + (size_t)r * ELLW;
    int oc = 0;
#pragma unroll
    for (int seg = 0; seg < 2; seg++) {
        int base = seg * 256 + lane * 8;
        int pc[8];
        if (base < c) {
            uint4 q = inv4[seg * 32 + lane];
            unsigned short e[8] = {
                (unsigned short)(q.x & 0xffff), (unsigned short)(q.x >> 16),
                (unsigned short)(q.y & 0xffff), (unsigned short)(q.y >> 16),
                (unsigned short)(q.z & 0xffff), (unsigned short)(q.z >> 16),
                (unsigned short)(q.w & 0xffff), (unsigned short)(q.w >> 16) };
#pragma unroll
            for (int u = 0; u < 8; u++)
                pc[u] = (base + u < c) ? g_pos1[e[u]] : -1;
        } else {
#pragma unroll
            for (int u = 0; u < 8; u++) pc[u] = -1;
        }
        int myn = 0;
#pragma unroll
        for (int u = 0; u < 8; u++) myn += (pc[u] >= 0);
        int inc = myn;
#pragma unroll
        for (int off = 1; off < 32; off <<= 1) {
            int t = __shfl_up_sync(0xffffffffu, inc, off);
            if (lane >= off) inc += t;
        }
        int wbase = oc + (inc - myn);
        int tot   = __shfl_sync(0xffffffffu, inc, 31);
#pragma unroll
        for (int u = 0; u < 8; u++) {
            if (pc[u] >= 0) { out[wbase] = (unsigned short)pc[u]; wbase++; }
        }
        oc += tot;
    }
    float dinv1 = rsqrtf((float)oc + 1.0f + EPSV);
    if (lane == 0) {
        g_cnt1[r]  = oc;
        g_dinv1[r] = dinv1;
    }
    // fused mm2: Y = d1 .* (X1[idx1] @ W2)
    float x1v = g_X1[src * FD + lane];
    float acc = 0.f;
#pragma unroll
    for (int kk = 0; kk < FD; kk++)
        acc += __shfl_sync(0xffffffffu, x1v, kk) * sW[kk * FD + lane];
    g_Y[r * FD + lane] = dinv1 * acc;
}

// ------- spmm2: X2 = relu(d1∘((A1+I) Y)), fused scores2 -----------------
__global__ void k_spmm2(const float* __restrict__ s2) {
    __shared__ float ssv[FD];
    if (threadIdx.x < FD) ssv[threadIdx.x] = s2[threadIdx.x];
    __syncthreads();
    int row  = blockIdx.x * 8 + (threadIdx.x >> 5);
    int lane = threadIdx.x & 31;
    const unsigned short* cols = g_ell1 + (size_t)row * ELLW;
    const uint4* cp = reinterpret_cast<const uint4*>(cols);
    int c = g_cnt1[row];
    float acc = g_Y[row * FD + lane];  // self
    int nv = c >> 3;
    for (int i = 0; i < nv; i++) {
        uint4 q = cp[i];
        int c0 = q.x & 0xffff, c1 = q.x >> 16;
        int c2 = q.y & 0xffff, c3 = q.y >> 16;
        int c4 = q.z & 0xffff, c5 = q.z >> 16;
        int c6 = q.w & 0xffff, c7 = q.w >> 16;
        float v0 = __ldg(&g_Y[c0 * FD + lane]);
        float v1 = __ldg(&g_Y[c1 * FD + lane]);
        float v2 = __ldg(&g_Y[c2 * FD + lane]);
        float v3 = __ldg(&g_Y[c3 * FD + lane]);
        float v4 = __ldg(&g_Y[c4 * FD + lane]);
        float v5 = __ldg(&g_Y[c5 * FD + lane]);
        float v6 = __ldg(&g_Y[c6 * FD + lane]);
        float v7 = __ldg(&g_Y[c7 * FD + lane]);
        acc += ((v0 + v1) + (v2 + v3)) + ((v4 + v5) + (v6 + v7));
    }
    for (int t = nv * 8; t < c; t++) acc += __ldg(&g_Y[cols[t] * FD + lane]);
    float ov = fmaxf(g_dinv1[row] * acc, 0.f);
    g_X2[row * FD + lane] = ov;
    float p = ov * ssv[lane];
#pragma unroll
    for (int o = 16; o > 0; o >>= 1) p += __shfl_down_sync(0xffffffffu, p, o);
    if (lane == 0) g_sc[row] = p;
}

// ------- spmm3 + fused mm4: Y2[idx1[r]] = d∘(X3_r @ W4) -----------------
// X3_r = relu(d1 .* ( ((A1+I)(md∘X2))_r @ W3 )) computed in registers and
// consumed immediately — no X3 store, no separate mm4 kernel.
__global__ void k_spmm3(const float* __restrict__ W3,
                        const float* __restrict__ W4) {
    __shared__ float sW[FD * FD];
    __shared__ float sw0[FD], sw1[FD];
    __shared__ float sS[8][FD];
    for (int i = threadIdx.x; i < FD * FD; i += blockDim.x) sW[i] = W3[i];
    if (threadIdx.x < FD) {
        sw0[threadIdx.x] = W4[threadIdx.x * 2];
        sw1[threadIdx.x] = W4[threadIdx.x * 2 + 1];
    }
    __syncthreads();
    int w    = threadIdx.x >> 5;
    int row  = blockIdx.x * 8 + w;
    int lane = threadIdx.x & 31;
    const unsigned short* cols = g_ell1 + (size_t)row * ELLW;
    const uint4* cp = reinterpret_cast<const uint4*>(cols);
    int c = g_cnt1[row];
    float acc = g_md[row] * g_X2[row * FD + lane];  // self term
    int nv = c >> 3;
    for (int i = 0; i < nv; i++) {
        uint4 q = cp[i];
        int c0 = q.x & 0xffff, c1 = q.x >> 16;
        int c2 = q.y & 0xffff, c3 = q.y >> 16;
        int c4 = q.z & 0xffff, c5 = q.z >> 16;
        int c6 = q.w & 0xffff, c7 = q.w >> 16;
        acc += __ldg(&g_md[c0]) * __ldg(&g_X2[c0 * FD + lane]);
        acc += __ldg(&g_md[c1]) * __ldg(&g_X2[c1 * FD + lane]);
        acc += __ldg(&g_md[c2]) * __ldg(&g_X2[c2 * FD + lane]);
        acc += __ldg(&g_md[c3]) * __ldg(&g_X2[c3 * FD + lane]);
        acc += __ldg(&g_md[c4]) * __ldg(&g_X2[c4 * FD + lane]);
        acc += __ldg(&g_md[c5]) * __ldg(&g_X2[c5 * FD + lane]);
        acc += __ldg(&g_md[c6]) * __ldg(&g_X2[c6 * FD + lane]);
        acc += __ldg(&g_md[c7]) * __ldg(&g_X2[c7 * FD + lane]);
    }
    for (int t = nv * 8; t < c; t++) {
        int cc = cols[t];
        acc += __ldg(&g_md[cc]) * __ldg(&g_X2[cc * FD + lane]);
    }
    sS[w][lane] = acc;
    __syncwarp();
    float o = 0.f;
#pragma unroll
    for (int kk = 0; kk < FD; kk++) o += sS[w][kk] * sW[kk * FD + lane];
    float x3 = fmaxf(g_dinv1[row] * o, 0.f);
    // fused mm4: i = idx1[row]; Y2[i] = d[i] * (x3 @ W4)
    int gi = g_idx1[row];
    float a0 = x3 * sw0[lane];
    float a1 = x3 * sw1[lane];
#pragma unroll
    for (int off = 16; off > 0; off >>= 1) {
        a0 += __shfl_down_sync(0xffffffffu, a0, off);
        a1 += __shfl_down_sync(0xffffffffu, a1, off);
    }
    if (lane == 0) {
        float dg = g_dinv[gi];
        float2* y2 = reinterpret_cast<float2*>(g_Y2);
        y2[gi] = make_float2(dg * a0, dg * a1);
    }
}

// ---------------- final 2-wide SpMM + softmax (16 lanes/row) ------------
__global__ void k_out(float* __restrict__ out) {
    int row = blockIdx.x * 16 + (threadIdx.x >> 4);
    int l   = threadIdx.x & 15;
    const unsigned short* cols = g_ell + (size_t)row * ELLW;
    int c = g_cnt[row];
    const float2* y2 = reinterpret_cast<const float2*>(g_Y2);
    float s0 = 0.f, s1 = 0.f;
    for (int t = l; t < c; t += 16) {
        float2 v = __ldg(&y2[cols[t]]);
        s0 += v.x; s1 += v.y;
    }
#pragma unroll
    for (int o = 8; o > 0; o >>= 1) {
        s0 += __shfl_down_sync(0xffffffffu, s0, o, 16);
        s1 += __shfl_down_sync(0xffffffffu, s1, o, 16);
    }
    if (l == 0) {
        float d  = g_dinv[row];
        float2 self = y2[row];
        float z0 = d * (s0 + self.x);
        float z1 = d * (s1 + self.y);
        float m  = fmaxf(z0, z1);
        float e0 = expf(z0 - m), e1 = expf(z1 - m);
        float inv = 1.f / (e0 + e1);
        out[row * 2]     = e0 * inv;
        out[row * 2 + 1] = e1 * inv;
    }
}

// ---------------- launch ------------------------------------------------
extern "C" void kernel_launch(void* const* d_in, const int* in_sizes, int n_in,
                              void* d_out, int out_size) {
    const float* x  = (const float*)d_in[0];
    const float* a  = (const float*)d_in[1];
    const float* W1 = (const float*)d_in[2];
    const float* W2 = (const float*)d_in[3];
    const float* W3 = (const float*)d_in[4];
    const float* W4 = (const float*)d_in[5];
    const float* s1 = (const float*)d_in[6];
    const float* s2 = (const float*)d_in[7];
    float* out = (float*)d_out;

    k_build_ell<<<N0 / 8, 256>>>(a, x);              // ELL + deg + Yx=d∘x
    k_spmm1<<<N0 / 8, 256>>>(W1, s1);                // X1 (16-wide gather) + scores1
    k_topk<8192, 8><<<1, 1024>>>(NK1, 0);            // idx1/pos1 + Y2 pre-zero
    k_sub_ell<<<NK1 / 8, 256>>>(W2);                 // ELL1 + d1 + Y=d1∘(X1[idx1]@W2)
    k_spmm2<<<NK1 / 8, 256>>>(s2);                   // X2 + scores2
    k_topk<4096, 4><<<1, 1024>>>(NK2, 1);            // pos2 + md
    k_spmm3<<<NK1 / 8, 256>>>(W3, W4);               // X3 + fused mm4 → Y2
    k_out<<<N0 / 16, 256>>>(out);                    // softmax(A_norm @ Y2)
}

// round 13
// speedup vs baseline: 1.0971x; 1.0201x over previous
#include <cuda_runtime.h>

#define N0   8192
#define NK1  4096
#define NK2  2048
#define FD   32
#define FIN  16
#define ELLW 512
#define EPSV 1e-10f

// ---------------- device scratch (static; no allocation) ----------------
__device__ unsigned short g_ell [(size_t)N0  * ELLW]; // 8 MB
__device__ unsigned short g_ell1[(size_t)NK1 * ELLW]; // 4 MB
__device__ int   g_cnt  [N0];
__device__ int   g_cnt1 [NK1];
__device__ float g_dinv [N0];
__device__ float g_dinv1[NK1];
__device__ float g_Yx[N0 * FIN];  // d ∘ x  (16-wide gather payload, layer 1)
__device__ float g_Y [NK1 * FD];  // d1 ∘ (X1[idx1] @ W2) (layer-2 payload)
__device__ float g_X1[N0 * FD];
__device__ float g_X2[NK1 * FD];
__device__ float g_md[NK1];       // mask * d1 (for fused spmm3)
__device__ float g_sc[N0];
__device__ float g_Y2[N0 * 2];
__device__ int g_idx1[NK1];
__device__ int g_pos1[N0];
__device__ int g_idx2[NK2];
__device__ int g_pos2[NK1];

// ------- 1) ELL build + degrees + Yx = d∘x (one 256MB streaming read) ---
__global__ void k_build_ell(const float* __restrict__ a,
                            const float* __restrict__ x) {
    int row  = blockIdx.x * 8 + (threadIdx.x >> 5);
    int lane = threadIdx.x & 31;
    const float4* arow = reinterpret_cast<const float4*>(a + (size_t)row * N0);
    unsigned short* out = g_ell + (size_t)row * ELLW;
    float4 bufA[8], bufB[8];
#pragma unroll
    for (int j = 0; j < 8; j++) bufA[j] = __ldcs(&arow[j * 32 + lane]);
    int cnt = 0;
#pragma unroll
    for (int it = 0; it < 8; it++) {
        float4* cur = (it & 1) ? bufB : bufA;
        float4* nxt = (it & 1) ? bufA : bufB;
        if (it < 7) {
#pragma unroll
            for (int j = 0; j < 8; j++)
                nxt[j] = __ldcs(&arow[(it + 1) * 256 + j * 32 + lane]);
        }
        unsigned msk = 0u;
#pragma unroll
        for (int j = 0; j < 8; j++) {
            float vs[4] = { cur[j].x, cur[j].y, cur[j].z, cur[j].w };
#pragma unroll
            for (int s = 0; s < 4; s++)
                msk |= (vs[s] != 0.0f ? 1u : 0u) << (j * 4 + s);
        }
        int nl = __popc(msk);
        int inc = nl;
#pragma unroll
        for (int off = 1; off < 32; off <<= 1) {
            int t = __shfl_up_sync(0xffffffffu, inc, off);
            if (lane >= off) inc += t;
        }
        int base = cnt + (inc - nl);
        int tot  = __shfl_sync(0xffffffffu, inc, 31);
        int cbase = it * 1024 + lane * 4;
        while (msk) {
            int b = __ffs(msk) - 1;
            msk &= msk - 1;
            int col = cbase + (b >> 2) * 128 + (b & 3);
            if (base < ELLW) out[base] = (unsigned short)col;
            base++;
        }
        cnt += tot;
    }
    float dinv = rsqrtf((float)cnt + 1.0f + EPSV);
    if (lane == 0) {
        g_cnt[row]  = cnt < ELLW ? cnt : ELLW;
        g_dinv[row] = dinv;
    }
    if (lane < FIN) g_Yx[row * FIN + lane] = dinv * x[row * FIN + lane];
}

// ------- spmm1: X1 = relu( (d∘(A+I)(d∘x)) @ W1 ), fused scores1 ---------
__global__ void k_spmm1(const float* __restrict__ W1,
                        const float* __restrict__ s1) {
    __shared__ float sW[FIN * FD];
    __shared__ float ssv[FD];
    __shared__ float sS[8][FIN];
    for (int i = threadIdx.x; i < FIN * FD; i += blockDim.x) sW[i] = W1[i];
    if (threadIdx.x < FD) ssv[threadIdx.x] = s1[threadIdx.x];
    cudaGridDependencySynchronize();   // PDL: wait for build
    __syncthreads();
    int w    = threadIdx.x >> 5;
    int row  = blockIdx.x * 8 + w;
    int lane = threadIdx.x & 31;
    int h    = lane & 15;
    int half = lane >> 4;
    const unsigned short* cols = g_ell + (size_t)row * ELLW;
    const uint4* cp = reinterpret_cast<const uint4*>(cols);
    int c = g_cnt[row];
    float acc = (half == 0) ? g_Yx[row * FIN + h] : 0.f;  // self term
    int nv = c >> 3;
    for (int i = 0; i < nv; i++) {
        uint4 q = cp[i];
        int c0, c1, c2, c3;
        if (half == 0) { c0 = q.x & 0xffff; c1 = q.x >> 16; c2 = q.y & 0xffff; c3 = q.y >> 16; }
        else           { c0 = q.z & 0xffff; c1 = q.z >> 16; c2 = q.w & 0xffff; c3 = q.w >> 16; }
        float v0 = __ldg(&g_Yx[c0 * FIN + h]);
        float v1 = __ldg(&g_Yx[c1 * FIN + h]);
        float v2 = __ldg(&g_Yx[c2 * FIN + h]);
        float v3 = __ldg(&g_Yx[c3 * FIN + h]);
        acc += (v0 + v1) + (v2 + v3);
    }
    for (int t = nv * 8 + half; t < c; t += 2)
        acc += __ldg(&g_Yx[cols[t] * FIN + h]);
    acc += __shfl_down_sync(0xffffffffu, acc, 16);
    if (half == 0) sS[w][h] = g_dinv[row] * acc;
    __syncwarp();
    float o = 0.f;
#pragma unroll
    for (int kk = 0; kk < FIN; kk++) o += sS[w][kk] * sW[kk * FD + lane];
    o = fmaxf(o, 0.f);
    g_X1[row * FD + lane] = o;
    float p = o * ssv[lane];
#pragma unroll
    for (int off = 16; off > 0; off >>= 1) p += __shfl_down_sync(0xffffffffu, p, off);
    if (lane == 0) g_sc[row] = p;
}

// ------- top-k: radix-select threshold + stable lowest-index ties -------
// Round 0 uses per-warp privatized histograms (pitch 257 vs bank conflicts).
template <int SIZE, int CH>
__global__ void k_topk(int k, int osel) {
    __shared__ unsigned ph[32 * 257];   // per-warp round-0 histograms
    __shared__ unsigned hist[256];
    __shared__ unsigned warpsum[32];
    __shared__ unsigned s_byte;
    __shared__ int s_kr;
    int tid  = threadIdx.x;
    int lane = tid & 31;
    int wid  = tid >> 5;
    for (int i = tid; i < 32 * 257; i += 1024) ph[i] = 0u;
    cudaGridDependencySynchronize();   // PDL: wait for scores
    unsigned keys[CH];
#pragma unroll
    for (int c = 0; c < CH; c++) {
        unsigned u = __float_as_uint(g_sc[tid * CH + c]);
        keys[c] = (u & 0x80000000u) ? ~u : (u | 0x80000000u); // order-preserving
    }
    __syncthreads();
    // round 0: privatized histogram
#pragma unroll
    for (int c = 0; c < CH; c++)
        atomicAdd(&ph[wid * 257 + (keys[c] >> 24)], 1u);
    __syncthreads();
    if (tid < 256) {
        unsigned s = 0;
#pragma unroll
        for (int w = 0; w < 32; w++) s += ph[w * 257 + tid];
        hist[tid] = s;
    }
    __syncthreads();
    unsigned prefix = 0;
    int kr = k;
    for (int round = 0; round < 4; round++) {
        int sh = 24 - round * 8;
        if (round > 0) {
            if (tid < 256) hist[tid] = 0u;
            __syncthreads();
            unsigned pmask = 0xffffffffu << (sh + 8);
#pragma unroll
            for (int c = 0; c < CH; c++) {
                if ((keys[c] & pmask) == prefix)
                    atomicAdd(&hist[(keys[c] >> sh) & 0xffu], 1u);
            }
            __syncthreads();
        }
        if (wid == 0) {
            unsigned h[8];
#pragma unroll
            for (int i = 0; i < 8; i++) h[i] = hist[lane * 8 + i];
            unsigned loc[8];
            unsigned run = 0;
#pragma unroll
            for (int i = 7; i >= 0; i--) { run += h[i]; loc[i] = run; }
            unsigned s = run;
#pragma unroll
            for (int off = 1; off < 32; off <<= 1) {
                unsigned t = __shfl_down_sync(0xffffffffu, s, off);
                if (lane + off < 32) s += t;
            }
            unsigned higher = s - run;
#pragma unroll
            for (int i = 0; i < 8; i++) {
                unsigned S = loc[i] + higher;
                if (S >= (unsigned)kr && (S - h[i]) < (unsigned)kr) {
                    s_byte = (unsigned)(lane * 8 + i);
                    s_kr   = kr - (int)(S - h[i]);
                }
            }
        }
        __syncthreads();
        prefix |= (s_byte << sh);
        kr = s_kr;
        __syncthreads();
    }
    unsigned thr = prefix; // exact k-th largest key

    int nstrict = 0, neq = 0;
#pragma unroll
    for (int c = 0; c < CH; c++) {
        nstrict += (keys[c] > thr);
        neq     += (keys[c] == thr);
    }
    unsigned v = ((unsigned)nstrict << 16) | (unsigned)neq;
    unsigned sc = v;
#pragma unroll
    for (int off = 1; off < 32; off <<= 1) {
        unsigned t = __shfl_up_sync(0xffffffffu, sc, off);
        if (lane >= off) sc += t;
    }
    if (lane == 31) warpsum[wid] = sc;
    __syncthreads();
    if (wid == 0) {
        unsigned w = warpsum[lane];
        unsigned ws = w;
#pragma unroll
        for (int off = 1; off < 32; off <<= 1) {
            unsigned t = __shfl_up_sync(0xffffffffu, ws, off);
            if (lane >= off) ws += t;
        }
        warpsum[lane] = ws;
    }
    __syncthreads();
    unsigned incl  = sc + (wid > 0 ? warpsum[wid - 1] : 0u);
    unsigned total = warpsum[31];
    unsigned excl  = incl - v;
    int st = (int)(excl >> 16);
    int eq = (int)(excl & 0xffffu);
    int budget = k - (int)(total >> 16); // ties filled by lowest index
    int* idx = (osel == 0) ? g_idx1 : g_idx2;
    int* pos = (osel == 0) ? g_pos1 : g_pos2;
#pragma unroll
    for (int c = 0; c < CH; c++) {
        unsigned key = keys[c];
        int i = tid * CH + c;
        bool isS = (key > thr);
        bool isE = (key == thr);
        bool sel = isS || (isE && eq < budget);
        int p = -1;
        if (sel) {
            int rank = st + (eq < budget ? eq : budget);
            idx[rank] = i;
            p = rank;
        }
        pos[i] = p;
        st += isS;
        eq += isE;
        if (osel == 1) g_md[i] = (p >= 0) ? g_dinv1[i] : 0.f; // mask*d1 for spmm3
    }
    // pre-zero Y2 (runs before spmm3; selected entries overwritten there)
    if (osel == 0) {
        float2* y2 = reinterpret_cast<float2*>(g_Y2);
        for (int i = tid; i < N0; i += 1024) y2[i] = make_float2(0.f, 0.f);
    }
}

// ------- sub-graph ELL: A1p = a[idx1][:,idx1]; fused mm2 ----------------
__global__ void k_sub_ell(const float* __restrict__ W2) {
    __shared__ float sW[FD * FD];
    for (int i = threadIdx.x; i < FD * FD; i += blockDim.x) sW[i] = W2[i];
    cudaGridDependencySynchronize();   // PDL: wait for topk1
    __syncthreads();
    int r    = blockIdx.x * 8 + (threadIdx.x >> 5);
    int lane = threadIdx.x & 31;
    int src  = g_idx1[r];
    int c    = g_cnt[src];
    const uint4* inv4 = reinterpret_cast<const uint4*>(g_ell + (size_t)src * ELLW);
    unsigned short* out = g_ell1 + (size_t)r * ELLW;
    int oc = 0;
#pragma unroll
    for (int seg = 0; seg < 2; seg++) {
        int base = seg * 256 + lane * 8;
        int pc[8];
        if (base < c) {
            uint4 q = inv4[seg * 32 + lane];
            unsigned short e[8] = {
                (unsigned short)(q.x & 0xffff), (unsigned short)(q.x >> 16),
                (unsigned short)(q.y & 0xffff), (unsigned short)(q.y >> 16),
                (unsigned short)(q.z & 0xffff), (unsigned short)(q.z >> 16),
                (unsigned short)(q.w & 0xffff), (unsigned short)(q.w >> 16) };
#pragma unroll
            for (int u = 0; u < 8; u++)
                pc[u] = (base + u < c) ? g_pos1[e[u]] : -1;
        } else {
#pragma unroll
            for (int u = 0; u < 8; u++) pc[u] = -1;
        }
        int myn = 0;
#pragma unroll
        for (int u = 0; u < 8; u++) myn += (pc[u] >= 0);
        int inc = myn;
#pragma unroll
        for (int off = 1; off < 32; off <<= 1) {
            int t = __shfl_up_sync(0xffffffffu, inc, off);
            if (lane >= off) inc += t;
        }
        int wbase = oc + (inc - myn);
        int tot   = __shfl_sync(0xffffffffu, inc, 31);
#pragma unroll
        for (int u = 0; u < 8; u++) {
            if (pc[u] >= 0) { out[wbase] = (unsigned short)pc[u]; wbase++; }
        }
        oc += tot;
    }
    float dinv1 = rsqrtf((float)oc + 1.0f + EPSV);
    if (lane == 0) {
        g_cnt1[r]  = oc;
        g_dinv1[r] = dinv1;
    }
    // fused mm2: Y = d1 .* (X1[idx1] @ W2)
    float x1v = g_X1[src * FD + lane];
    float acc = 0.f;
#pragma unroll
    for (int kk = 0; kk < FD; kk++)
        acc += __shfl_sync(0xffffffffu, x1v, kk) * sW[kk * FD + lane];
    g_Y[r * FD + lane] = dinv1 * acc;
}

// ------- spmm2: X2 = relu(d1∘((A1+I) Y)), fused scores2 -----------------
__global__ void k_spmm2(const float* __restrict__ s2) {
    __shared__ float ssv[FD];
    if (threadIdx.x < FD) ssv[threadIdx.x] = s2[threadIdx.x];
    cudaGridDependencySynchronize();   // PDL: wait for sub_ell
    __syncthreads();
    int row  = blockIdx.x * 8 + (threadIdx.x >> 5);
    int lane = threadIdx.x & 31;
    const unsigned short* cols = g_ell1 + (size_t)row * ELLW;
    const uint4* cp = reinterpret_cast<const uint4*>(cols);
    int c = g_cnt1[row];
    float acc = g_Y[row * FD + lane];  // self
    int nv = c >> 3;
    for (int i = 0; i < nv; i++) {
        uint4 q = cp[i];
        int c0 = q.x & 0xffff, c1 = q.x >> 16;
        int c2 = q.y & 0xffff, c3 = q.y >> 16;
        int c4 = q.z & 0xffff, c5 = q.z >> 16;
        int c6 = q.w & 0xffff, c7 = q.w >> 16;
        float v0 = __ldg(&g_Y[c0 * FD + lane]);
        float v1 = __ldg(&g_Y[c1 * FD + lane]);
        float v2 = __ldg(&g_Y[c2 * FD + lane]);
        float v3 = __ldg(&g_Y[c3 * FD + lane]);
        float v4 = __ldg(&g_Y[c4 * FD + lane]);
        float v5 = __ldg(&g_Y[c5 * FD + lane]);
        float v6 = __ldg(&g_Y[c6 * FD + lane]);
        float v7 = __ldg(&g_Y[c7 * FD + lane]);
        acc += ((v0 + v1) + (v2 + v3)) + ((v4 + v5) + (v6 + v7));
    }
    for (int t = nv * 8; t < c; t++) acc += __ldg(&g_Y[cols[t] * FD + lane]);
    float ov = fmaxf(g_dinv1[row] * acc, 0.f);
    g_X2[row * FD + lane] = ov;
    float p = ov * ssv[lane];
#pragma unroll
    for (int o = 16; o > 0; o >>= 1) p += __shfl_down_sync(0xffffffffu, p, o);
    if (lane == 0) g_sc[row] = p;
}

// ------- spmm3 + fused mm4: Y2[idx1[r]] = d∘(X3_r @ W4) -----------------
__global__ void k_spmm3(const float* __restrict__ W3,
                        const float* __restrict__ W4) {
    __shared__ float sW[FD * FD];
    __shared__ float sw0[FD], sw1[FD];
    __shared__ float sS[8][FD];
    for (int i = threadIdx.x; i < FD * FD; i += blockDim.x) sW[i] = W3[i];
    if (threadIdx.x < FD) {
        sw0[threadIdx.x] = W4[threadIdx.x * 2];
        sw1[threadIdx.x] = W4[threadIdx.x * 2 + 1];
    }
    cudaGridDependencySynchronize();   // PDL: wait for topk2
    __syncthreads();
    int w    = threadIdx.x >> 5;
    int row  = blockIdx.x * 8 + w;
    int lane = threadIdx.x & 31;
    const unsigned short* cols = g_ell1 + (size_t)row * ELLW;
    const uint4* cp = reinterpret_cast<const uint4*>(cols);
    int c = g_cnt1[row];
    float acc = g_md[row] * g_X2[row * FD + lane];  // self term
    int nv = c >> 3;
    for (int i = 0; i < nv; i++) {
        uint4 q = cp[i];
        int c0 = q.x & 0xffff, c1 = q.x >> 16;
        int c2 = q.y & 0xffff, c3 = q.y >> 16;
        int c4 = q.z & 0xffff, c5 = q.z >> 16;
        int c6 = q.w & 0xffff, c7 = q.w >> 16;
        acc += __ldg(&g_md[c0]) * __ldg(&g_X2[c0 * FD + lane]);
        acc += __ldg(&g_md[c1]) * __ldg(&g_X2[c1 * FD + lane]);
        acc += __ldg(&g_md[c2]) * __ldg(&g_X2[c2 * FD + lane]);
        acc += __ldg(&g_md[c3]) * __ldg(&g_X2[c3 * FD + lane]);
        acc += __ldg(&g_md[c4]) * __ldg(&g_X2[c4 * FD + lane]);
        acc += __ldg(&g_md[c5]) * __ldg(&g_X2[c5 * FD + lane]);
        acc += __ldg(&g_md[c6]) * __ldg(&g_X2[c6 * FD + lane]);
        acc += __ldg(&g_md[c7]) * __ldg(&g_X2[c7 * FD + lane]);
    }
    for (int t = nv * 8; t < c; t++) {
        int cc = cols[t];
        acc += __ldg(&g_md[cc]) * __ldg(&g_X2[cc * FD + lane]);
    }
    sS[w][lane] = acc;
    __syncwarp();
    float o = 0.f;
#pragma unroll
    for (int kk = 0; kk < FD; kk++) o += sS[w][kk] * sW[kk * FD + lane];
    float x3 = fmaxf(g_dinv1[row] * o, 0.f);
    // fused mm4: i = idx1[row]; Y2[i] = d[i] * (x3 @ W4)
    int gi = g_idx1[row];
    float a0 = x3 * sw0[lane];
    float a1 = x3 * sw1[lane];
#pragma unroll
    for (int off = 16; off > 0; off >>= 1) {
        a0 += __shfl_down_sync(0xffffffffu, a0, off);
        a1 += __shfl_down_sync(0xffffffffu, a1, off);
    }
    if (lane == 0) {
        float dg = g_dinv[gi];
        float2* y2 = reinterpret_cast<float2*>(g_Y2);
        y2[gi] = make_float2(dg * a0, dg * a1);
    }
}

// ---------------- final 2-wide SpMM + softmax (16 lanes/row) ------------
__global__ void k_out(float* __restrict__ out) {
    cudaGridDependencySynchronize();   // PDL: wait for spmm3
    int row = blockIdx.x * 16 + (threadIdx.x >> 4);
    int l   = threadIdx.x & 15;
    const unsigned short* cols = g_ell + (size_t)row * ELLW;
    int c = g_cnt[row];
    const float2* y2 = reinterpret_cast<const float2*>(g_Y2);
    float s0 = 0.f, s1 = 0.f;
    for (int t = l; t < c; t += 16) {
        float2 v = __ldg(&y2[cols[t]]);
        s0 += v.x; s1 += v.y;
    }
#pragma unroll
    for (int o = 8; o > 0; o >>= 1) {
        s0 += __shfl_down_sync(0xffffffffu, s0, o, 16);
        s1 += __shfl_down_sync(0xffffffffu, s1, o, 16);
    }
    if (l == 0) {
        float d  = g_dinv[row];
        float2 self = y2[row];
        float z0 = d * (s0 + self.x);
        float z1 = d * (s1 + self.y);
        float m  = fmaxf(z0, z1);
        float e0 = expf(z0 - m), e1 = expf(z1 - m);
        float inv = 1.f / (e0 + e1);
        out[row * 2]     = e0 * inv;
        out[row * 2 + 1] = e1 * inv;
    }
}

// ---------------- PDL launch helper -------------------------------------
template <typename... Args>
static inline void pdl_launch(dim3 g, dim3 b, void (*kern)(Args...), Args... a) {
    cudaLaunchConfig_t cfg = {};
    cfg.gridDim = g;
    cfg.blockDim = b;
    cudaLaunchAttribute at[1];
    at[0].id = cudaLaunchAttributeProgrammaticStreamSerialization;
    at[0].val.programmaticStreamSerializationAllowed = 1;
    cfg.attrs = at;
    cfg.numAttrs = 1;
    cudaLaunchKernelEx(&cfg, kern, a...);
}

// ---------------- launch ------------------------------------------------
extern "C" void kernel_launch(void* const* d_in, const int* in_sizes, int n_in,
                              void* d_out, int out_size) {
    const float* x  = (const float*)d_in[0];
    const float* a  = (const float*)d_in[1];
    const float* W1 = (const float*)d_in[2];
    const float* W2 = (const float*)d_in[3];
    const float* W3 = (const float*)d_in[4];
    const float* W4 = (const float*)d_in[5];
    const float* s1 = (const float*)d_in[6];
    const float* s2 = (const float*)d_in[7];
    float* out = (float*)d_out;

    k_build_ell<<<N0 / 8, 256>>>(a, x);                        // ELL + deg + Yx
    pdl_launch(dim3(N0 / 8), dim3(256), k_spmm1, W1, s1);      // X1 + scores1
    pdl_launch(dim3(1), dim3(1024), k_topk<8192, 8>, NK1, 0);  // idx1/pos1 + Y2 zero
    pdl_launch(dim3(NK1 / 8), dim3(256), k_sub_ell, W2);       // ELL1 + d1 + Y
    pdl_launch(dim3(NK1 / 8), dim3(256), k_spmm2, s2);         // X2 + scores2
    pdl_launch(dim3(1), dim3(1024), k_topk<4096, 4>, NK2, 1);  // pos2 + md
    pdl_launch(dim3(NK1 / 8), dim3(256), k_spmm3, W3, W4);     // X3 + mm4 → Y2
    pdl_launch(dim3(N0 / 16), dim3(256), k_out, out);          // softmax(A_norm @ Y2)
}